// round 6
// baseline (speedup 1.0000x reference)
#include <cuda_runtime.h>
#include <math.h>

#define Bq 4
#define Nq 512
#define DIN 128
#define F 64
#define NN (Nq*Nq)
#define ALPHA 0.2f
#define MSPLIT 4
#define MCHUNK (Nq/MSPLIT)     // 128

// scratch
__device__ float g_h[Bq*Nq*F];
__device__ float g_s1[Bq*Nq];
__device__ float g_t[Bq*Nq];
__device__ float g_part[MSPLIT*Bq*Nq*F];   // 2MB partial AV
__device__ float g_psum[MSPLIT*Bq*Nq];     // partial row sums

// ---------------------------------------------------------------------------
// Kernel A: h = x@W + b ; s1 = h.a1 ; t = h.a2.
// Register-tiled: thread = (f4 quad, row). Per k: 1 LDG.128 + 1 LDS + 4 FFMA.
// 16 rows/block, 256 thr, grid 128 (single wave).
// ---------------------------------------------------------------------------
__global__ __launch_bounds__(256) void gat_h_kernel(
    const float* __restrict__ x, const float* __restrict__ W,
    const float* __restrict__ bias, const float* __restrict__ a)
{
    __shared__ __align__(16) float xs[16*DIN];  // 8KB

    int tid   = threadIdx.x;
    int f4    = tid & 15;           // feature quad 0..15 (features f4*4..+3)
    int rslot = tid >> 4;           // 0..15
    int row0  = blockIdx.x * 16;
    int row   = row0 + rslot;

    // stage x rows: 512 float4, 2 per thread
    {
        const float4* src = (const float4*)(x + (long)row0*DIN);
        float4* dst = (float4*)xs;
        dst[tid]       = src[tid];
        dst[tid + 256] = src[tid + 256];
    }
    __syncthreads();

    const float4* W4 = (const float4*)W;     // [k][16 quads]
    float4 acc = ((const float4*)bias)[f4];
    const float* xr = xs + rslot*DIN;

    #pragma unroll 8
    for (int k = 0; k < DIN; ++k) {
        float4 w  = W4[k*16 + f4];
        float  xk = xr[k];
        acc.x += xk*w.x; acc.y += xk*w.y; acc.z += xk*w.z; acc.w += xk*w.w;
    }

    ((float4*)g_h)[(long)row*16 + f4] = acc;

    // s1/t: 16-lane (one row per half-warp) shuffle reduction
    float4 a1 = ((const float4*)a)[f4];
    float4 a2 = ((const float4*)a)[16 + f4];
    float s1 = acc.x*a1.x + acc.y*a1.y + acc.z*a1.z + acc.w*a1.w;
    float t  = acc.x*a2.x + acc.y*a2.y + acc.z*a2.z + acc.w*a2.w;
    #pragma unroll
    for (int o = 8; o; o >>= 1) {
        s1 += __shfl_xor_sync(0xffffffffu, s1, o);
        t  += __shfl_xor_sync(0xffffffffu, t,  o);
    }
    if (f4 == 0) { g_s1[row] = s1; g_t[row] = t; }
}

// ---------------------------------------------------------------------------
// Kernel B: 8 rows x 128-m chunk per block. 256 threads, grid 1024.
// Fused: masked exp(leakyrelu(logits)) + partial sums + partial AV.
// ---------------------------------------------------------------------------
__global__ __launch_bounds__(256) void gat_attn_kernel(const int* __restrict__ adj)
{
    __shared__ float s1s[Nq];
    __shared__ float ts [Nq];
    __shared__ __align__(16) float buf[4096];   // probs[8][128] (4KB) then red (16KB)
    float (*probs)[MCHUNK] = (float(*)[MCHUNK])buf;

    int tid  = threadIdx.x;
    int lane = tid & 31;
    int wid  = tid >> 5;                 // 0..7
    int bid  = blockIdx.x;
    int ms   = bid & 3;
    int rb   = (bid >> 2) & 63;
    int b    = bid >> 8;
    int n0   = rb << 3;
    int m0   = ms * MCHUNK;

    for (int i = tid; i < Nq; i += 256) {
        s1s[i] = g_s1[b*Nq + i];
        ts [i] = g_t [b*Nq + i];
    }
    __syncthreads();

    // ---- phase 1: exp(leakyrelu(logits)) masked, + row partial sums ----
    {
        int n  = n0 + wid;
        int ma = m0 + lane*4;            // absolute m, 4 per thread
        const int4 av = *(const int4*)(adj + ((long)b*Nq + n)*Nq + ma);
        int avv[4] = {av.x, av.y, av.z, av.w};
        float4 p4;
        float* pp = (float*)&p4;
        float sum = 0.f;
        #pragma unroll
        for (int j = 0; j < 4; ++j) {
            int m  = ma + j;
            int q1 = 2*(n*Nq + m);
            int idx1 = (q1   < NN) ? (q1   >> 9) : ((q1   - NN) & (Nq-1));
            int idx2 = (q1+1 < NN) ? ((q1+1)>> 9) : ((q1+1 - NN) & (Nq-1));
            float e = s1s[idx1] + ts[idx2];
            e = (e > 0.0f) ? e : ALPHA*e;
            float p = (avv[j] > 0) ? __expf(e) : 0.0f;
            pp[j] = p; sum += p;
        }
        *(float4*)&probs[wid][lane*4] = p4;
        #pragma unroll
        for (int o = 16; o; o >>= 1) sum += __shfl_xor_sync(0xffffffffu, sum, o);
        if (lane == 0) g_psum[(ms*Bq + b)*Nq + n] = sum;
    }
    __syncthreads();

    // ---- phase 2: partial AV. warp = 16 contiguous m, lane = f2 ----
    float2 acc[8];
    #pragma unroll
    for (int r = 0; r < 8; ++r) acc[r] = make_float2(0.f, 0.f);

    const float2* h2 = (const float2*)(g_h + (long)b*Nq*F);
    #pragma unroll
    for (int kc = 0; kc < 4; ++kc) {
        int mloc = wid*16 + kc*4;
        int mabs = m0 + mloc;
        float2 hv0 = h2[(mabs+0)*32 + lane];
        float2 hv1 = h2[(mabs+1)*32 + lane];
        float2 hv2 = h2[(mabs+2)*32 + lane];
        float2 hv3 = h2[(mabs+3)*32 + lane];
        #pragma unroll
        for (int r = 0; r < 8; ++r) {
            float4 p = *(const float4*)&probs[r][mloc];
            acc[r].x += p.x*hv0.x + p.y*hv1.x + p.z*hv2.x + p.w*hv3.x;
            acc[r].y += p.x*hv0.y + p.y*hv1.y + p.z*hv2.y + p.w*hv3.y;
        }
    }
    __syncthreads();                      // probs dead; buf becomes red (16KB)

    float2* red = (float2*)buf;           // [8 g][8 r][32 f2]
    #pragma unroll
    for (int r = 0; r < 8; ++r)
        red[(wid*8 + r)*32 + lane] = acc[r];
    __syncthreads();

    // reduce over 8 groups, store partial
    {
        int r = wid;
        float2 o = make_float2(0.f, 0.f);
        #pragma unroll
        for (int g = 0; g < 8; ++g) {
            float2 v = red[(g*8 + r)*32 + lane];
            o.x += v.x; o.y += v.y;
        }
        ((float2*)g_part)[((long)(ms*Bq + b)*Nq + n0 + r)*32 + lane] = o;
    }
}

// ---------------------------------------------------------------------------
// Kernel C: combine partials, normalize, elu. 256 blocks x 256 thr.
// ---------------------------------------------------------------------------
__global__ __launch_bounds__(256) void gat_combine_kernel(float* __restrict__ out)
{
    int gid = blockIdx.x*256 + threadIdx.x;   // 0..65535
    int row = gid >> 5;                       // b*Nq + n, 0..2047
    int f2  = gid & 31;

    const float2* part2 = (const float2*)g_part;
    float2 o = make_float2(0.f, 0.f);
    float  s = 0.f;
    #pragma unroll
    for (int ms = 0; ms < MSPLIT; ++ms) {
        float2 v = part2[((long)ms*Bq*Nq + row)*32 + f2];
        o.x += v.x; o.y += v.y;
        s += g_psum[ms*Bq*Nq + row];
    }
    float inv = 1.0f / s;
    o.x *= inv; o.y *= inv;
    o.x = (o.x > 0.0f) ? o.x : expm1f(o.x);
    o.y = (o.y > 0.0f) ? o.y : expm1f(o.y);
    ((float2*)out)[(long)row*32 + f2] = o;
}

// ---------------------------------------------------------------------------
extern "C" void kernel_launch(void* const* d_in, const int* in_sizes, int n_in,
                              void* d_out, int out_size)
{
    const float* x    = (const float*)d_in[0];
    const int*   adj  = (const int*)  d_in[1];
    const float* W    = (const float*)d_in[2];
    const float* bias = (const float*)d_in[3];
    const float* a    = (const float*)d_in[4];
    float* out = (float*)d_out;

    gat_h_kernel<<<(Bq*Nq)/16, 256>>>(x, W, bias, a);
    gat_attn_kernel<<<Bq*64*MSPLIT, 256>>>(adj);
    gat_combine_kernel<<<(Bq*Nq*32)/256, 256>>>(out);
}

// round 7
// speedup vs baseline: 1.2296x; 1.2296x over previous
#include <cuda_runtime.h>
#include <math.h>

#define Bq 4
#define Nq 512
#define DIN 128
#define F 64
#define NN (Nq*Nq)
#define ALPHA 0.2f
#define MSPLIT 4
#define MCHUNK (Nq/MSPLIT)     // 128
#define KS 2
#define KC (DIN/KS)            // 64

// scratch
__device__ float g_hpart[KS*Bq*Nq*F];      // h k-partials
__device__ float g_s1p[KS*Bq*Nq];
__device__ float g_tp [KS*Bq*Nq];
__device__ float g_part[MSPLIT*Bq*Nq*F];   // partial AV
__device__ float g_psum[MSPLIT*Bq*Nq];     // partial row sums

// ---------------------------------------------------------------------------
// Kernel A: split-k partial  h_kc = x[:,kc] @ W[kc,:] (+b on kc=0); partial s1/t.
// 4 rows/block, 2 warps/row, 64 k per block. Grid 1024 (512 rowblk x 2 kc).
// ---------------------------------------------------------------------------
__global__ __launch_bounds__(256) void gat_h_kernel(
    const float* __restrict__ x, const float* __restrict__ W,
    const float* __restrict__ bias, const float* __restrict__ a)
{
    __shared__ __align__(16) float xs[4*KC];    // 1KB
    __shared__ float red[4][2][2];

    int bid   = blockIdx.x;
    int kc    = bid & 1;
    int rb    = bid >> 1;
    int row0  = rb * 4;
    int k0    = kc * KC;

    int tid   = threadIdx.x;
    int lane  = tid & 31;
    int wid   = tid >> 5;          // 0..7
    int rloc  = wid >> 1;          // 0..3
    int fhalf = wid & 1;
    int row   = row0 + rloc;
    int f     = fhalf*32 + lane;

    if (tid < 64) {
        int r = tid >> 4;          // row 0..3
        int c = tid & 15;          // float4 col 0..15
        ((float4*)xs)[tid] = *(const float4*)(x + (long)(row0 + r)*DIN + k0 + c*4);
    }
    __syncthreads();

    const float* xsr = xs + rloc*KC;
    const float* Wp  = W + (long)k0*F;
    float acc = (kc == 0) ? bias[f] : 0.0f;
    #pragma unroll 8
    for (int k = 0; k < KC; ++k)
        acc += xsr[k] * Wp[k*F + f];

    g_hpart[(long)kc*Bq*Nq*F + (long)row*F + f] = acc;

    float s1p = acc * a[f];
    float tp  = acc * a[F + f];
    #pragma unroll
    for (int o = 16; o; o >>= 1) {
        s1p += __shfl_xor_sync(0xffffffffu, s1p, o);
        tp  += __shfl_xor_sync(0xffffffffu, tp,  o);
    }
    if (lane == 0) { red[rloc][fhalf][0] = s1p; red[rloc][fhalf][1] = tp; }
    __syncthreads();
    if (tid < 4) {
        g_s1p[kc*Bq*Nq + row0 + tid] = red[tid][0][0] + red[tid][1][0];
        g_tp [kc*Bq*Nq + row0 + tid] = red[tid][0][1] + red[tid][1][1];
    }
}

// ---------------------------------------------------------------------------
// Kernel B: 8 rows x 128-m chunk per block. 256 threads, grid 1024.
// Combines h/s1/t k-partials inline.
// ---------------------------------------------------------------------------
__global__ __launch_bounds__(256) void gat_attn_kernel(const int* __restrict__ adj)
{
    __shared__ float s1s[Nq];
    __shared__ float ts [Nq];
    __shared__ __align__(16) float buf[4096];   // probs[8][128] (4KB) then red (16KB)
    float (*probs)[MCHUNK] = (float(*)[MCHUNK])buf;

    int tid  = threadIdx.x;
    int lane = tid & 31;
    int wid  = tid >> 5;                 // 0..7
    int bid  = blockIdx.x;
    int ms   = bid & 3;
    int rb   = (bid >> 2) & 63;
    int b    = bid >> 8;
    int n0   = rb << 3;
    int m0   = ms * MCHUNK;

    for (int i = tid; i < Nq; i += 256) {
        s1s[i] = g_s1p[b*Nq + i] + g_s1p[Bq*Nq + b*Nq + i];
        ts [i] = g_tp [b*Nq + i] + g_tp [Bq*Nq + b*Nq + i];
    }
    __syncthreads();

    // ---- phase 1: exp(leakyrelu(logits)) masked, + row partial sums ----
    {
        int n  = n0 + wid;
        int ma = m0 + lane*4;
        const int4 av = *(const int4*)(adj + ((long)b*Nq + n)*Nq + ma);
        int avv[4] = {av.x, av.y, av.z, av.w};
        float4 p4;
        float* pp = (float*)&p4;
        float sum = 0.f;
        #pragma unroll
        for (int j = 0; j < 4; ++j) {
            int m  = ma + j;
            int q1 = 2*(n*Nq + m);
            int idx1 = (q1   < NN) ? (q1   >> 9) : ((q1   - NN) & (Nq-1));
            int idx2 = (q1+1 < NN) ? ((q1+1)>> 9) : ((q1+1 - NN) & (Nq-1));
            float e = s1s[idx1] + ts[idx2];
            e = (e > 0.0f) ? e : ALPHA*e;
            float p = (avv[j] > 0) ? __expf(e) : 0.0f;
            pp[j] = p; sum += p;
        }
        *(float4*)&probs[wid][lane*4] = p4;
        #pragma unroll
        for (int o = 16; o; o >>= 1) sum += __shfl_xor_sync(0xffffffffu, sum, o);
        if (lane == 0) g_psum[(ms*Bq + b)*Nq + n] = sum;
    }
    __syncthreads();

    // ---- phase 2: partial AV with inline h-combine ----
    float2 acc[8];
    #pragma unroll
    for (int r = 0; r < 8; ++r) acc[r] = make_float2(0.f, 0.f);

    const float2* h2a = (const float2*)(g_hpart + (long)b*Nq*F);
    const float2* h2b = (const float2*)(g_hpart + (long)Bq*Nq*F + (long)b*Nq*F);
    #pragma unroll
    for (int kcc = 0; kcc < 4; ++kcc) {
        int mloc = wid*16 + kcc*4;
        int mabs = m0 + mloc;
        float2 u0 = h2a[(mabs+0)*32 + lane], v0 = h2b[(mabs+0)*32 + lane];
        float2 u1 = h2a[(mabs+1)*32 + lane], v1 = h2b[(mabs+1)*32 + lane];
        float2 u2 = h2a[(mabs+2)*32 + lane], v2 = h2b[(mabs+2)*32 + lane];
        float2 u3 = h2a[(mabs+3)*32 + lane], v3 = h2b[(mabs+3)*32 + lane];
        float2 hv0 = make_float2(u0.x+v0.x, u0.y+v0.y);
        float2 hv1 = make_float2(u1.x+v1.x, u1.y+v1.y);
        float2 hv2 = make_float2(u2.x+v2.x, u2.y+v2.y);
        float2 hv3 = make_float2(u3.x+v3.x, u3.y+v3.y);
        #pragma unroll
        for (int r = 0; r < 8; ++r) {
            float4 p = *(const float4*)&probs[r][mloc];
            acc[r].x += p.x*hv0.x + p.y*hv1.x + p.z*hv2.x + p.w*hv3.x;
            acc[r].y += p.x*hv0.y + p.y*hv1.y + p.z*hv2.y + p.w*hv3.y;
        }
    }
    __syncthreads();                      // probs dead; buf becomes red (16KB)

    float2* red = (float2*)buf;           // [8 g][8 r][32 f2]
    #pragma unroll
    for (int r = 0; r < 8; ++r)
        red[(wid*8 + r)*32 + lane] = acc[r];
    __syncthreads();

    {
        int r = wid;
        float2 o = make_float2(0.f, 0.f);
        #pragma unroll
        for (int g = 0; g < 8; ++g) {
            float2 v = red[(g*8 + r)*32 + lane];
            o.x += v.x; o.y += v.y;
        }
        ((float2*)g_part)[((long)(ms*Bq + b)*Nq + n0 + r)*32 + lane] = o;
    }
}

// ---------------------------------------------------------------------------
// Kernel C: combine partials, normalize, elu. 256 blocks x 256 thr.
// ---------------------------------------------------------------------------
__global__ __launch_bounds__(256) void gat_combine_kernel(float* __restrict__ out)
{
    int gid = blockIdx.x*256 + threadIdx.x;   // 0..65535
    int row = gid >> 5;                       // b*Nq + n
    int f2  = gid & 31;

    const float2* part2 = (const float2*)g_part;
    float2 o = make_float2(0.f, 0.f);
    float  s = 0.f;
    #pragma unroll
    for (int ms = 0; ms < MSPLIT; ++ms) {
        float2 v = part2[((long)ms*Bq*Nq + row)*32 + f2];
        o.x += v.x; o.y += v.y;
        s += g_psum[ms*Bq*Nq + row];
    }
    float inv = 1.0f / s;
    o.x *= inv; o.y *= inv;
    o.x = (o.x > 0.0f) ? o.x : expm1f(o.x);
    o.y = (o.y > 0.0f) ? o.y : expm1f(o.y);
    ((float2*)out)[(long)row*32 + f2] = o;
}

// ---------------------------------------------------------------------------
extern "C" void kernel_launch(void* const* d_in, const int* in_sizes, int n_in,
                              void* d_out, int out_size)
{
    const float* x    = (const float*)d_in[0];
    const int*   adj  = (const int*)  d_in[1];
    const float* W    = (const float*)d_in[2];
    const float* bias = (const float*)d_in[3];
    const float* a    = (const float*)d_in[4];
    float* out = (float*)d_out;

    gat_h_kernel<<<(Bq*Nq/4)*KS, 256>>>(x, W, bias, a);
    gat_attn_kernel<<<Bq*64*MSPLIT, 256>>>(adj);
    gat_combine_kernel<<<(Bq*Nq*32)/256, 256>>>(out);
}